// round 9
// baseline (speedup 1.0000x reference)
#include <cuda_runtime.h>
#include <cuda_bf16.h>
#include <cstdint>

#define NN 40000
#define EE 640000

// ---------------- static device scratch (no allocs allowed) ----------------
__device__ __align__(16) unsigned g_AB[(size_t)NN * 128]; // bf16 pairs: [node][128 u32]; u32 0..63 = a, 64..127 = b
__device__ __align__(16) float    g_S[EE];                // raw edge scores, later alpha
__device__ __align__(16) float    g_Y[(size_t)NN * 128];  // y = x + local
__device__ __align__(16) unsigned g_WhT[128 * 32];        // Wh^T bf16 pairs: [n][32]  (k pairs)
__device__ __align__(16) unsigned g_WcT[256 * 64];        // combined node-W^T bf16 pairs: [ncomb][64]
__device__ __align__(16) float    g_G[128 * 128];         // I + ft_w
__device__ float    g_bias[128];                          // Wh_b + Wn_b
__device__ unsigned g_maxenc;
__device__ float    g_Z;
__device__ int      g_idx64;
// CSR-by-src
__device__ int g_deg[NN];
__device__ int g_off[NN + 1];
__device__ int g_cur[NN];
__device__ int g_eidx[EE];

// ---------------- helpers ----------------
__device__ __forceinline__ unsigned packbf(float a, float b) {
    unsigned lo = (unsigned)__bfloat16_as_ushort(__float2bfloat16_rn(a));
    unsigned hi = (unsigned)__bfloat16_as_ushort(__float2bfloat16_rn(b));
    return lo | (hi << 16);
}
__device__ __forceinline__ float2 bf2(unsigned u) {
    float2 r;
    r.x = __uint_as_float(u << 16);
    r.y = __uint_as_float(u & 0xffff0000u);
    return r;
}
// order-preserving float<->uint encode for atomicMax
__device__ __forceinline__ unsigned encf(float f) {
    unsigned b = __float_as_uint(f);
    return (b & 0x80000000u) ? ~b : (b | 0x80000000u);
}
__device__ __forceinline__ float decf(unsigned u) {
    unsigned b = (u & 0x80000000u) ? (u & 0x7fffffffu) : ~u;
    return __uint_as_float(b);
}
__device__ __forceinline__ void mma16816(float& c0, float& c1, float& c2, float& c3,
                                         unsigned a0, unsigned a1, unsigned a2, unsigned a3,
                                         unsigned b0, unsigned b1) {
    asm volatile(
        "mma.sync.aligned.m16n8k16.row.col.f32.bf16.bf16.f32 "
        "{%0,%1,%2,%3},{%4,%5,%6,%7},{%8,%9},{%0,%1,%2,%3};\n"
        : "+f"(c0), "+f"(c1), "+f"(c2), "+f"(c3)
        : "r"(a0), "r"(a1), "r"(a2), "r"(a3), "r"(b0), "r"(b1));
}
// packed fp32x2 FMA (FFMA2 — 2x fp32 FMA throughput, PTX-only pattern)
__device__ __forceinline__ void fma2(unsigned long long& c, unsigned long long a,
                                     unsigned long long b) {
    asm("fma.rn.f32x2 %0, %1, %2, %0;" : "+l"(c) : "l"(a), "l"(b));
}
__device__ __forceinline__ unsigned long long pk2(float x, float y) {
    unsigned long long r;
    asm("mov.b64 %0, {%1,%2};" : "=l"(r) : "f"(x), "f"(y));
    return r;
}
__device__ __forceinline__ float2 upk2(unsigned long long v) {
    float2 f;
    asm("mov.b64 {%0,%1}, %2;" : "=f"(f.x), "=f"(f.y) : "l"(v));
    return f;
}

// ---------------- prep: weight transposes/conversions, flags, zero deg ----------------
__global__ void k_prep(const float* __restrict__ Whw, const float* __restrict__ Whb,
                       const float* __restrict__ Wnw, const float* __restrict__ Wnb,
                       const float* __restrict__ ftw, const int* __restrict__ eiw) {
    int gid = blockIdx.x * blockDim.x + threadIdx.x; // 40960 threads
    if (gid < NN) g_deg[gid] = 0;
    // WhT pairs: 128 n x 32 k-pairs
    if (gid < 4096) {
        int n = gid >> 5, k2 = gid & 31;
        int k = k2 * 2;
        g_WhT[gid] = packbf(Whw[k * 128 + n], Whw[(k + 1) * 128 + n]);
    }
    // WcT pairs: 256 ncomb x 64 k-pairs. ncomb = part*128 + hid
    if (gid < 16384) {
        int ncomb = gid >> 6, k2 = gid & 63;
        int k = k2 * 2;
        int row0 = (ncomb >> 7) * 128 + k;
        int col = ncomb & 127;
        g_WcT[gid] = packbf(Wnw[row0 * 128 + col], Wnw[(row0 + 1) * 128 + col]);
    }
    // G = I + ft_w
    if (gid < 16384) {
        g_G[gid] = ftw[gid] + (((gid >> 7) == (gid & 127)) ? 1.0f : 0.0f);
    }
    if (gid < 128) g_bias[gid] = Whb[gid] + Wnb[gid];
    if (gid == 0) {
        int o = 0;
#pragma unroll
        for (int i = 0; i < 64; i++) o |= eiw[2 * i + 1];
        g_idx64 = (o == 0) ? 1 : 0;
        g_maxenc = 0u;
        g_Z = 0.0f;
    }
}

// ---------------- node projection: g_AB = bf16( x @ [Wn_a | Wn_b] ) via mma ----------------
__global__ __launch_bounds__(128) void k_node(const float* __restrict__ x) {
    extern __shared__ unsigned smu[];
    unsigned* sX = smu;              // 64 rows x 68 (pad) u32 (k pairs)
    unsigned* sW = smu + 64 * 68;    // 128 n-rows x 68 (pad) u32
    int t = threadIdx.x;
    int node0 = blockIdx.x * 64;
    int part = blockIdx.y;           // 0 -> a cols, 1 -> b cols
    const float2* xp = (const float2*)x;
#pragma unroll
    for (int j = 0; j < 32; j++) {
        int idx = t + j * 128;       // 4096
        int r = idx >> 6, c = idx & 63;
        float2 f = xp[(size_t)(node0 + r) * 64 + c];
        sX[r * 68 + c] = packbf(f.x, f.y);
    }
#pragma unroll
    for (int j = 0; j < 64; j++) {
        int idx = t + j * 128;       // 8192
        int n = idx >> 6, k = idx & 63;
        sW[n * 68 + k] = g_WcT[(size_t)(part * 128 + n) * 64 + k];
    }
    __syncthreads();
    int warp = t >> 5, lane = t & 31, g = lane >> 2, q = lane & 3;
    int m0 = warp * 16;
#pragma unroll
    for (int nt = 0; nt < 16; nt++) {
        float c0 = 0.f, c1 = 0.f, c2 = 0.f, c3 = 0.f;
#pragma unroll
        for (int kc = 0; kc < 8; kc++) {
            unsigned a0 = sX[(m0 + g) * 68 + kc * 8 + q];
            unsigned a1 = sX[(m0 + g + 8) * 68 + kc * 8 + q];
            unsigned a2 = sX[(m0 + g) * 68 + kc * 8 + q + 4];
            unsigned a3 = sX[(m0 + g + 8) * 68 + kc * 8 + q + 4];
            unsigned b0 = sW[(nt * 8 + g) * 68 + kc * 8 + q];
            unsigned b1 = sW[(nt * 8 + g) * 68 + kc * 8 + q + 4];
            mma16816(c0, c1, c2, c3, a0, a1, a2, a3, b0, b1);
        }
        int node = node0 + m0 + g;
        int u = part * 64 + nt * 4 + q;
        g_AB[(size_t)node * 128 + u] = packbf(c0, c1);
        g_AB[(size_t)(node + 8) * 128 + u] = packbf(c2, c3);
    }
}

// ---------------- fused edge kernel: scores + block max ----------------
__global__ __launch_bounds__(128) void k_edge(const float* __restrict__ ea,
                                              const void* __restrict__ ei,
                                              const float* __restrict__ we) {
    __shared__ unsigned sWh[128 * 36];
    __shared__ float swe[128];
    __shared__ float sbias[128];
    __shared__ float smax[4];
    int t = threadIdx.x;
#pragma unroll
    for (int j = 0; j < 32; j++) {
        int idx = t + j * 128;
        int n = idx >> 5, k = idx & 31;
        sWh[n * 36 + k] = g_WhT[idx];
    }
    swe[t & 127] = we[t & 127];
    sbias[t & 127] = g_bias[t & 127];
    __syncthreads();

    int warp = t >> 5, lane = t & 31, g = lane >> 2, q = lane & 3;
    int e0 = (blockIdx.x * 4 + warp) * 16;
    int r0 = e0 + g, r1 = r0 + 8;
    int s0, d0, s1, d1;
    if (g_idx64) {
        const long long* p = (const long long*)ei;
        s0 = (int)p[r0]; d0 = (int)p[(long long)EE + r0];
        s1 = (int)p[r1]; d1 = (int)p[(long long)EE + r1];
    } else {
        const int* p = (const int*)ei;
        s0 = p[r0]; d0 = p[EE + r0];
        s1 = p[r1]; d1 = p[EE + r1];
    }
    unsigned a[4][4];
    const float2* ear0 = (const float2*)ea + (size_t)r0 * 32;
    const float2* ear1 = (const float2*)ea + (size_t)r1 * 32;
#pragma unroll
    for (int kc = 0; kc < 4; kc++) {
        float2 f;
        f = ear0[kc * 8 + q];     a[kc][0] = packbf(f.x, f.y);
        f = ear1[kc * 8 + q];     a[kc][1] = packbf(f.x, f.y);
        f = ear0[kc * 8 + q + 4]; a[kc][2] = packbf(f.x, f.y);
        f = ear1[kc * 8 + q + 4]; a[kc][3] = packbf(f.x, f.y);
    }
    const unsigned* as0p = g_AB + (size_t)s0 * 128;
    const unsigned* bd0p = g_AB + (size_t)d0 * 128 + 64;
    const unsigned* as1p = g_AB + (size_t)s1 * 128;
    const unsigned* bd1p = g_AB + (size_t)d1 * 128 + 64;
    float sacc0 = 0.f, sacc1 = 0.f;
#pragma unroll
    for (int nt = 0; nt < 16; nt++) {
        float c0 = 0.f, c1 = 0.f, c2 = 0.f, c3 = 0.f;
#pragma unroll
        for (int kc = 0; kc < 4; kc++) {
            unsigned b0 = sWh[(nt * 8 + g) * 36 + kc * 8 + q];
            unsigned b1 = sWh[(nt * 8 + g) * 36 + kc * 8 + q + 4];
            mma16816(c0, c1, c2, c3, a[kc][0], a[kc][1], a[kc][2], a[kc][3], b0, b1);
        }
        int n0 = nt * 8 + q * 2;
        float wx = swe[n0], wy = swe[n0 + 1];
        float bx = sbias[n0], by = sbias[n0 + 1];
        int u = nt * 4 + q;
        float2 A0 = bf2(as0p[u]); float2 B0 = bf2(bd0p[u]);
        float2 A1 = bf2(as1p[u]); float2 B1 = bf2(bd1p[u]);
        float v;
        v = c0 + A0.x + B0.x + bx; v = fmaxf(v, 0.f); sacc0 = fmaf(v, wx, sacc0);
        v = c1 + A0.y + B0.y + by; v = fmaxf(v, 0.f); sacc0 = fmaf(v, wy, sacc0);
        v = c2 + A1.x + B1.x + bx; v = fmaxf(v, 0.f); sacc1 = fmaf(v, wx, sacc1);
        v = c3 + A1.y + B1.y + by; v = fmaxf(v, 0.f); sacc1 = fmaf(v, wy, sacc1);
    }
    sacc0 += __shfl_xor_sync(0xffffffffu, sacc0, 1);
    sacc0 += __shfl_xor_sync(0xffffffffu, sacc0, 2);
    sacc1 += __shfl_xor_sync(0xffffffffu, sacc1, 1);
    sacc1 += __shfl_xor_sync(0xffffffffu, sacc1, 2);
    if (q == 0) { g_S[r0] = sacc0; g_S[r1] = sacc1; }
    float mx = fmaxf(sacc0, sacc1);
#pragma unroll
    for (int o = 16; o; o >>= 1) mx = fmaxf(mx, __shfl_xor_sync(0xffffffffu, mx, o));
    if (lane == 0) smax[warp] = mx;
    __syncthreads();
    if (t == 0) {
        float m = fmaxf(fmaxf(smax[0], smax[1]), fmaxf(smax[2], smax[3]));
        atomicMax(&g_maxenc, encf(m));
    }
}

// ---------------- Z = sum exp(s - m) ----------------
__global__ void k_Zred() {
    __shared__ float ssum[8];
    float m = decf(g_maxenc);
    int gid = blockIdx.x * blockDim.x + threadIdx.x;
    int stride = gridDim.x * blockDim.x;
    float s = 0.f;
    for (int i = gid; i < EE; i += stride) s += __expf(g_S[i] - m);
#pragma unroll
    for (int o = 16; o; o >>= 1) s += __shfl_xor_sync(0xffffffffu, s, o);
    if ((threadIdx.x & 31) == 0) ssum[threadIdx.x >> 5] = s;
    __syncthreads();
    if (threadIdx.x == 0) {
        float b = 0.f;
        for (int i = 0; i < 8; i++) b += ssum[i];
        atomicAdd(&g_Z, b);
    }
}

// ---------------- CSR build: histogram of src ----------------
__global__ void k_hist(const void* __restrict__ ei) {
    int e = blockIdx.x * blockDim.x + threadIdx.x;
    if (e >= EE) return;
    int s = g_idx64 ? (int)((const long long*)ei)[e] : ((const int*)ei)[e];
    atomicAdd(&g_deg[s], 1);
}

// ---------------- CSR build: exclusive scan (single block) ----------------
__global__ __launch_bounds__(1024) void k_scan() {
    __shared__ int smc[1024];
    int t = threadIdx.x;
    const int CH = 40; // 1024*40 = 40960 >= NN
    int base = t * CH;
    int s = 0;
#pragma unroll 8
    for (int i = 0; i < CH; i++) {
        int idx = base + i;
        s += (idx < NN) ? g_deg[idx] : 0;
    }
    smc[t] = s;
    __syncthreads();
    for (int off = 1; off < 1024; off <<= 1) {
        int v = (t >= off) ? smc[t - off] : 0;
        __syncthreads();
        smc[t] += v;
        __syncthreads();
    }
    int run = smc[t] - s; // exclusive prefix
    for (int i = 0; i < CH; i++) {
        int idx = base + i;
        if (idx < NN) {
            g_off[idx] = run;
            g_cur[idx] = run;
            run += g_deg[idx];
        }
    }
    if (t == 0) g_off[NN] = EE;
}

// ---------------- CSR fill + alpha = exp(s-m)/Z written in-place to g_S ----------------
__global__ void k_fill(const void* __restrict__ ei) {
    int e = blockIdx.x * blockDim.x + threadIdx.x;
    if (e >= EE) return;
    int s = g_idx64 ? (int)((const long long*)ei)[e] : ((const int*)ei)[e];
    int pos = atomicAdd(&g_cur[s], 1);
    g_eidx[pos] = e;
    float m = decf(g_maxenc);
    g_S[e] = __fdividef(__expf(g_S[e] - m), g_Z);
}

// ---------------- gather: y[n] = x[n] - sum_e alpha_e * x[dst_e], one warp per node ----------------
__global__ __launch_bounds__(256) void k_gather(const float4* __restrict__ x4,
                                                const void* __restrict__ ei) {
    int n = blockIdx.x * 8 + (threadIdx.x >> 5);
    if (n >= NN) return;
    int lane = threadIdx.x & 31;
    float4 acc = x4[(size_t)n * 32 + lane];
    int o0 = g_off[n], o1 = g_off[n + 1];
    const int* dst32 = (const int*)ei + EE;
    const long long* dst64 = (const long long*)ei + EE;
    bool w = (g_idx64 != 0);
    for (int o = o0; o < o1; o++) {
        int e = g_eidx[o];
        float a = g_S[e]; // alpha
        int d = w ? (int)dst64[e] : dst32[e];
        float4 xv = x4[(size_t)d * 32 + lane];
        acc.x = fmaf(-a, xv.x, acc.x);
        acc.y = fmaf(-a, xv.y, acc.y);
        acc.z = fmaf(-a, xv.z, acc.z);
        acc.w = fmaf(-a, xv.w, acc.w);
    }
    ((float4*)g_Y)[(size_t)n * 32 + lane] = acc;
}

// ---------------- out = y @ (I + ft_w) + ft_b  (fp32x2 FFMA2 tiled GEMM) ----------------
__global__ __launch_bounds__(256) void k_out(const float* __restrict__ ftb,
                                             float* __restrict__ out) {
    extern __shared__ float sm[];
    float* sG = sm;            // 128*128
    float* sYT = sm + 16384;   // 16 x 68 (k-major, padded)
    int t = threadIdx.x;
    int tx = t & 15, ty = t >> 4;
#pragma unroll
    for (int j = 0; j < 64; j++) sG[t + j * 256] = g_G[t + j * 256];
    unsigned long long acc[4][4];
#pragma unroll
    for (int i = 0; i < 4; i++)
#pragma unroll
        for (int j = 0; j < 4; j++) acc[i][j] = 0ull;
    int m0 = blockIdx.x * 64;
    for (int kc = 0; kc < 8; kc++) {
        __syncthreads();
#pragma unroll
        for (int j = 0; j < 4; j++) {
            int idx = t + j * 256;        // 1024
            int c = idx & 15, r = idx >> 4;
            sYT[c * 68 + r] = g_Y[(size_t)(m0 + r) * 128 + kc * 16 + c];
        }
        __syncthreads();
#pragma unroll
        for (int k = 0; k < 16; k++) {
            float4 av = *(float4*)(sYT + k * 68 + ty * 4);
            const unsigned long long* bp =
                (const unsigned long long*)(sG + (kc * 16 + k) * 128 + tx * 8);
            unsigned long long b0 = bp[0], b1 = bp[1], b2 = bp[2], b3 = bp[3];
            unsigned long long a0 = pk2(av.x, av.x);
            unsigned long long a1 = pk2(av.y, av.y);
            unsigned long long a2 = pk2(av.z, av.z);
            unsigned long long a3 = pk2(av.w, av.w);
            fma2(acc[0][0], a0, b0); fma2(acc[0][1], a0, b1);
            fma2(acc[0][2], a0, b2); fma2(acc[0][3], a0, b3);
            fma2(acc[1][0], a1, b0); fma2(acc[1][1], a1, b1);
            fma2(acc[1][2], a1, b2); fma2(acc[1][3], a1, b3);
            fma2(acc[2][0], a2, b0); fma2(acc[2][1], a2, b1);
            fma2(acc[2][2], a2, b2); fma2(acc[2][3], a2, b3);
            fma2(acc[3][0], a3, b0); fma2(acc[3][1], a3, b1);
            fma2(acc[3][2], a3, b2); fma2(acc[3][3], a3, b3);
        }
    }
    float4 fb0 = ((const float4*)ftb)[tx * 2];
    float4 fb1 = ((const float4*)ftb)[tx * 2 + 1];
#pragma unroll
    for (int i = 0; i < 4; i++) {
        float2 p0 = upk2(acc[i][0]), p1 = upk2(acc[i][1]);
        float2 p2 = upk2(acc[i][2]), p3 = upk2(acc[i][3]);
        float4 o0 = make_float4(p0.x + fb0.x, p0.y + fb0.y, p1.x + fb0.z, p1.y + fb0.w);
        float4 o1 = make_float4(p2.x + fb1.x, p2.y + fb1.y, p3.x + fb1.z, p3.y + fb1.w);
        float4* op = (float4*)(out + (size_t)(m0 + ty * 4 + i) * 128 + tx * 8);
        op[0] = o0;
        op[1] = o1;
    }
}

// ---------------- launch ----------------
extern "C" void kernel_launch(void* const* d_in, const int* in_sizes, int n_in,
                              void* d_out, int out_size) {
    const float* x   = (const float*)d_in[0];
    const void*  ei  = d_in[1];
    const float* ea  = (const float*)d_in[2];
    const float* Whw = (const float*)d_in[3];
    const float* Whb = (const float*)d_in[4];
    const float* Wnw = (const float*)d_in[5];
    const float* Wnb = (const float*)d_in[6];
    const float* we  = (const float*)d_in[7];
    const float* ftw = (const float*)d_in[8];
    const float* ftb = (const float*)d_in[9];
    float* out = (float*)d_out;

    cudaFuncSetAttribute(k_node, cudaFuncAttributeMaxDynamicSharedMemorySize, 52224);
    cudaFuncSetAttribute(k_out,  cudaFuncAttributeMaxDynamicSharedMemorySize, 69888);

    k_prep<<<160, 256>>>(Whw, Whb, Wnw, Wnb, ftw, (const int*)ei);
    k_node<<<dim3(625, 2), 128, 52224>>>(x);
    k_edge<<<10000, 128>>>(ea, ei, we);
    k_Zred<<<2500, 256>>>();
    k_hist<<<2500, 256>>>(ei);
    k_scan<<<1, 1024>>>();
    k_fill<<<2500, 256>>>(ei);
    k_gather<<<5000, 256>>>((const float4*)x, ei);
    k_out<<<625, 256, 69888>>>(ftb, out);
}

// round 10
// speedup vs baseline: 1.0298x; 1.0298x over previous
#include <cuda_runtime.h>
#include <cuda_bf16.h>
#include <cstdint>

#define NN 40000
#define EE 640000

// ---------------- static device scratch (no allocs allowed) ----------------
__device__ __align__(16) unsigned g_AB[(size_t)NN * 128]; // bf16 pairs: [node][128 u32]; u32 0..63 = a, 64..127 = b
__device__ __align__(16) float    g_S[EE];                // raw edge scores
__device__ __align__(16) float    g_Y[(size_t)NN * 128];  // y = x + local
__device__ __align__(16) unsigned g_WhT[128 * 32];        // Wh^T bf16 pairs: [n][32]  (k pairs)
__device__ __align__(16) unsigned g_WcT[256 * 64];        // combined node-W^T bf16 pairs: [ncomb][64]
__device__ __align__(16) float    g_G[128 * 128];         // I + ft_w
__device__ float    g_bias[128];                          // Wh_b + Wn_b
__device__ unsigned g_maxenc;
__device__ float    g_Z;
__device__ int      g_idx64;
// CSR-by-src
__device__ int  g_deg[NN];
__device__ int  g_off[NN + 1];
__device__ int  g_cur[NN];
__device__ __align__(8) uint2 g_edg[EE];                  // CSR-ordered {dst, bits(-alpha)}

// ---------------- helpers ----------------
__device__ __forceinline__ unsigned packbf(float a, float b) {
    unsigned lo = (unsigned)__bfloat16_as_ushort(__float2bfloat16_rn(a));
    unsigned hi = (unsigned)__bfloat16_as_ushort(__float2bfloat16_rn(b));
    return lo | (hi << 16);
}
__device__ __forceinline__ float2 bf2(unsigned u) {
    float2 r;
    r.x = __uint_as_float(u << 16);
    r.y = __uint_as_float(u & 0xffff0000u);
    return r;
}
// order-preserving float<->uint encode for atomicMax
__device__ __forceinline__ unsigned encf(float f) {
    unsigned b = __float_as_uint(f);
    return (b & 0x80000000u) ? ~b : (b | 0x80000000u);
}
__device__ __forceinline__ float decf(unsigned u) {
    unsigned b = (u & 0x80000000u) ? (u & 0x7fffffffu) : ~u;
    return __uint_as_float(b);
}
__device__ __forceinline__ void mma16816(float& c0, float& c1, float& c2, float& c3,
                                         unsigned a0, unsigned a1, unsigned a2, unsigned a3,
                                         unsigned b0, unsigned b1) {
    asm volatile(
        "mma.sync.aligned.m16n8k16.row.col.f32.bf16.bf16.f32 "
        "{%0,%1,%2,%3},{%4,%5,%6,%7},{%8,%9},{%0,%1,%2,%3};\n"
        : "+f"(c0), "+f"(c1), "+f"(c2), "+f"(c3)
        : "r"(a0), "r"(a1), "r"(a2), "r"(a3), "r"(b0), "r"(b1));
}
// packed fp32x2 FMA (FFMA2 — 2x fp32 FMA throughput, PTX-only pattern)
__device__ __forceinline__ void fma2(unsigned long long& c, unsigned long long a,
                                     unsigned long long b) {
    asm("fma.rn.f32x2 %0, %1, %2, %0;" : "+l"(c) : "l"(a), "l"(b));
}
__device__ __forceinline__ unsigned long long pk2(float x, float y) {
    unsigned long long r;
    asm("mov.b64 %0, {%1,%2};" : "=l"(r) : "f"(x), "f"(y));
    return r;
}
__device__ __forceinline__ float2 upk2(unsigned long long v) {
    float2 f;
    asm("mov.b64 {%0,%1}, %2;" : "=f"(f.x), "=f"(f.y) : "l"(v));
    return f;
}

// ---------------- prep: weight transposes/conversions, flags, zero deg ----------------
__global__ void k_prep(const float* __restrict__ Whw, const float* __restrict__ Whb,
                       const float* __restrict__ Wnw, const float* __restrict__ Wnb,
                       const float* __restrict__ ftw, const int* __restrict__ eiw) {
    int gid = blockIdx.x * blockDim.x + threadIdx.x; // 40960 threads
    if (gid < NN) g_deg[gid] = 0;
    // WhT pairs: 128 n x 32 k-pairs
    if (gid < 4096) {
        int n = gid >> 5, k2 = gid & 31;
        int k = k2 * 2;
        g_WhT[gid] = packbf(Whw[k * 128 + n], Whw[(k + 1) * 128 + n]);
    }
    // WcT pairs: 256 ncomb x 64 k-pairs. ncomb = part*128 + hid
    if (gid < 16384) {
        int ncomb = gid >> 6, k2 = gid & 63;
        int k = k2 * 2;
        int row0 = (ncomb >> 7) * 128 + k;
        int col = ncomb & 127;
        g_WcT[gid] = packbf(Wnw[row0 * 128 + col], Wnw[(row0 + 1) * 128 + col]);
    }
    // G = I + ft_w
    if (gid < 16384) {
        g_G[gid] = ftw[gid] + (((gid >> 7) == (gid & 127)) ? 1.0f : 0.0f);
    }
    if (gid < 128) g_bias[gid] = Whb[gid] + Wnb[gid];
    if (gid == 0) {
        int o = 0;
#pragma unroll
        for (int i = 0; i < 64; i++) o |= eiw[2 * i + 1];
        g_idx64 = (o == 0) ? 1 : 0;
        g_maxenc = 0u;
        g_Z = 0.0f;
    }
}

// ---------------- node projection: g_AB = bf16( x @ [Wn_a | Wn_b] ) via mma ----------------
__global__ __launch_bounds__(128) void k_node(const float* __restrict__ x) {
    extern __shared__ unsigned smu[];
    unsigned* sX = smu;              // 64 rows x 68 (pad) u32 (k pairs)
    unsigned* sW = smu + 64 * 68;    // 128 n-rows x 68 (pad) u32
    int t = threadIdx.x;
    int node0 = blockIdx.x * 64;
    int part = blockIdx.y;           // 0 -> a cols, 1 -> b cols
    const float2* xp = (const float2*)x;
#pragma unroll
    for (int j = 0; j < 32; j++) {
        int idx = t + j * 128;       // 4096
        int r = idx >> 6, c = idx & 63;
        float2 f = xp[(size_t)(node0 + r) * 64 + c];
        sX[r * 68 + c] = packbf(f.x, f.y);
    }
#pragma unroll
    for (int j = 0; j < 64; j++) {
        int idx = t + j * 128;       // 8192
        int n = idx >> 6, k = idx & 63;
        sW[n * 68 + k] = g_WcT[(size_t)(part * 128 + n) * 64 + k];
    }
    __syncthreads();
    int warp = t >> 5, lane = t & 31, g = lane >> 2, q = lane & 3;
    int m0 = warp * 16;
#pragma unroll
    for (int nt = 0; nt < 16; nt++) {
        float c0 = 0.f, c1 = 0.f, c2 = 0.f, c3 = 0.f;
#pragma unroll
        for (int kc = 0; kc < 8; kc++) {
            unsigned a0 = sX[(m0 + g) * 68 + kc * 8 + q];
            unsigned a1 = sX[(m0 + g + 8) * 68 + kc * 8 + q];
            unsigned a2 = sX[(m0 + g) * 68 + kc * 8 + q + 4];
            unsigned a3 = sX[(m0 + g + 8) * 68 + kc * 8 + q + 4];
            unsigned b0 = sW[(nt * 8 + g) * 68 + kc * 8 + q];
            unsigned b1 = sW[(nt * 8 + g) * 68 + kc * 8 + q + 4];
            mma16816(c0, c1, c2, c3, a0, a1, a2, a3, b0, b1);
        }
        int node = node0 + m0 + g;
        int u = part * 64 + nt * 4 + q;
        g_AB[(size_t)node * 128 + u] = packbf(c0, c1);
        g_AB[(size_t)(node + 8) * 128 + u] = packbf(c2, c3);
    }
}

// ---------------- fused edge kernel: scores + block max ----------------
__global__ __launch_bounds__(128) void k_edge(const float* __restrict__ ea,
                                              const void* __restrict__ ei,
                                              const float* __restrict__ we) {
    __shared__ unsigned sWh[128 * 36];
    __shared__ float swe[128];
    __shared__ float sbias[128];
    __shared__ float smax[4];
    int t = threadIdx.x;
#pragma unroll
    for (int j = 0; j < 32; j++) {
        int idx = t + j * 128;
        int n = idx >> 5, k = idx & 31;
        sWh[n * 36 + k] = g_WhT[idx];
    }
    swe[t & 127] = we[t & 127];
    sbias[t & 127] = g_bias[t & 127];
    __syncthreads();

    int warp = t >> 5, lane = t & 31, g = lane >> 2, q = lane & 3;
    int e0 = (blockIdx.x * 4 + warp) * 16;
    int r0 = e0 + g, r1 = r0 + 8;
    int s0, d0, s1, d1;
    if (g_idx64) {
        const long long* p = (const long long*)ei;
        s0 = (int)p[r0]; d0 = (int)p[(long long)EE + r0];
        s1 = (int)p[r1]; d1 = (int)p[(long long)EE + r1];
    } else {
        const int* p = (const int*)ei;
        s0 = p[r0]; d0 = p[EE + r0];
        s1 = p[r1]; d1 = p[EE + r1];
    }
    unsigned a[4][4];
    const float2* ear0 = (const float2*)ea + (size_t)r0 * 32;
    const float2* ear1 = (const float2*)ea + (size_t)r1 * 32;
#pragma unroll
    for (int kc = 0; kc < 4; kc++) {
        float2 f;
        f = ear0[kc * 8 + q];     a[kc][0] = packbf(f.x, f.y);
        f = ear1[kc * 8 + q];     a[kc][1] = packbf(f.x, f.y);
        f = ear0[kc * 8 + q + 4]; a[kc][2] = packbf(f.x, f.y);
        f = ear1[kc * 8 + q + 4]; a[kc][3] = packbf(f.x, f.y);
    }
    const unsigned* as0p = g_AB + (size_t)s0 * 128;
    const unsigned* bd0p = g_AB + (size_t)d0 * 128 + 64;
    const unsigned* as1p = g_AB + (size_t)s1 * 128;
    const unsigned* bd1p = g_AB + (size_t)d1 * 128 + 64;
    float sacc0 = 0.f, sacc1 = 0.f;
#pragma unroll
    for (int nt = 0; nt < 16; nt++) {
        float c0 = 0.f, c1 = 0.f, c2 = 0.f, c3 = 0.f;
#pragma unroll
        for (int kc = 0; kc < 4; kc++) {
            unsigned b0 = sWh[(nt * 8 + g) * 36 + kc * 8 + q];
            unsigned b1 = sWh[(nt * 8 + g) * 36 + kc * 8 + q + 4];
            mma16816(c0, c1, c2, c3, a[kc][0], a[kc][1], a[kc][2], a[kc][3], b0, b1);
        }
        int n0 = nt * 8 + q * 2;
        float wx = swe[n0], wy = swe[n0 + 1];
        float bx = sbias[n0], by = sbias[n0 + 1];
        int u = nt * 4 + q;
        float2 A0 = bf2(as0p[u]); float2 B0 = bf2(bd0p[u]);
        float2 A1 = bf2(as1p[u]); float2 B1 = bf2(bd1p[u]);
        float v;
        v = c0 + A0.x + B0.x + bx; v = fmaxf(v, 0.f); sacc0 = fmaf(v, wx, sacc0);
        v = c1 + A0.y + B0.y + by; v = fmaxf(v, 0.f); sacc0 = fmaf(v, wy, sacc0);
        v = c2 + A1.x + B1.x + bx; v = fmaxf(v, 0.f); sacc1 = fmaf(v, wx, sacc1);
        v = c3 + A1.y + B1.y + by; v = fmaxf(v, 0.f); sacc1 = fmaf(v, wy, sacc1);
    }
    sacc0 += __shfl_xor_sync(0xffffffffu, sacc0, 1);
    sacc0 += __shfl_xor_sync(0xffffffffu, sacc0, 2);
    sacc1 += __shfl_xor_sync(0xffffffffu, sacc1, 1);
    sacc1 += __shfl_xor_sync(0xffffffffu, sacc1, 2);
    if (q == 0) { g_S[r0] = sacc0; g_S[r1] = sacc1; }
    float mx = fmaxf(sacc0, sacc1);
#pragma unroll
    for (int o = 16; o; o >>= 1) mx = fmaxf(mx, __shfl_xor_sync(0xffffffffu, mx, o));
    if (lane == 0) smax[warp] = mx;
    __syncthreads();
    if (t == 0) {
        float m = fmaxf(fmaxf(smax[0], smax[1]), fmaxf(smax[2], smax[3]));
        atomicMax(&g_maxenc, encf(m));
    }
}

// ---------------- fused: src histogram + Z = sum exp(s - m) ----------------
__global__ void k_histZ(const void* __restrict__ ei) {
    __shared__ float ssum[8];
    float m = decf(g_maxenc);
    int gid = blockIdx.x * blockDim.x + threadIdx.x;
    float s = 0.f;
    if (gid < EE) {
        int src = g_idx64 ? (int)((const long long*)ei)[gid] : ((const int*)ei)[gid];
        atomicAdd(&g_deg[src], 1);
        s = __expf(g_S[gid] - m);
    }
#pragma unroll
    for (int o = 16; o; o >>= 1) s += __shfl_xor_sync(0xffffffffu, s, o);
    if ((threadIdx.x & 31) == 0) ssum[threadIdx.x >> 5] = s;
    __syncthreads();
    if (threadIdx.x == 0) {
        float b = 0.f;
#pragma unroll
        for (int i = 0; i < 8; i++) b += ssum[i];
        atomicAdd(&g_Z, b);
    }
}

// ---------------- CSR build: exclusive scan (single block) ----------------
__global__ __launch_bounds__(1024) void k_scan() {
    __shared__ int smc[1024];
    int t = threadIdx.x;
    const int CH = 40; // 1024*40 = 40960 >= NN
    int base = t * CH;
    int s = 0;
#pragma unroll 8
    for (int i = 0; i < CH; i++) {
        int idx = base + i;
        s += (idx < NN) ? g_deg[idx] : 0;
    }
    smc[t] = s;
    __syncthreads();
    for (int off = 1; off < 1024; off <<= 1) {
        int v = (t >= off) ? smc[t - off] : 0;
        __syncthreads();
        smc[t] += v;
        __syncthreads();
    }
    int run = smc[t] - s; // exclusive prefix
    for (int i = 0; i < CH; i++) {
        int idx = base + i;
        if (idx < NN) {
            g_off[idx] = run;
            g_cur[idx] = run;
            run += g_deg[idx];
        }
    }
    if (t == 0) g_off[NN] = EE;
}

// ---------------- CSR fill: packed {dst, -alpha} in CSR order ----------------
__global__ void k_fill(const void* __restrict__ ei) {
    int e = blockIdx.x * blockDim.x + threadIdx.x;
    if (e >= EE) return;
    int s, d;
    if (g_idx64) {
        const long long* p = (const long long*)ei;
        s = (int)p[e]; d = (int)p[(long long)EE + e];
    } else {
        const int* p = (const int*)ei;
        s = p[e]; d = p[EE + e];
    }
    float m = decf(g_maxenc);
    float na = -__fdividef(__expf(g_S[e] - m), g_Z); // pre-negated alpha
    int pos = atomicAdd(&g_cur[s], 1);
    g_edg[pos] = make_uint2((unsigned)d, __float_as_uint(na));
}

// ---------------- gather: y[n] = x[n] - sum alpha_e x[dst_e]; MLP-4 via shfl ----------------
__global__ __launch_bounds__(256) void k_gather(const float4* __restrict__ x4) {
    int n = blockIdx.x * 8 + (threadIdx.x >> 5);
    if (n >= NN) return;
    int lane = threadIdx.x & 31;
    float4 acc = x4[(size_t)n * 32 + lane];
    int o0 = g_off[n], o1 = g_off[n + 1];
    for (int base = o0; base < o1; base += 32) {
        int cnt = min(32, o1 - base);
        uint2 meta = make_uint2(0u, 0u);
        if (lane < cnt) meta = g_edg[base + lane];
        int j = 0;
        for (; j + 4 <= cnt; j += 4) {
            unsigned dA = __shfl_sync(0xffffffffu, meta.x, j);
            unsigned dB = __shfl_sync(0xffffffffu, meta.x, j + 1);
            unsigned dC = __shfl_sync(0xffffffffu, meta.x, j + 2);
            unsigned dD = __shfl_sync(0xffffffffu, meta.x, j + 3);
            float aA = __uint_as_float(__shfl_sync(0xffffffffu, meta.y, j));
            float aB = __uint_as_float(__shfl_sync(0xffffffffu, meta.y, j + 1));
            float aC = __uint_as_float(__shfl_sync(0xffffffffu, meta.y, j + 2));
            float aD = __uint_as_float(__shfl_sync(0xffffffffu, meta.y, j + 3));
            float4 vA = x4[(size_t)dA * 32 + lane];
            float4 vB = x4[(size_t)dB * 32 + lane];
            float4 vC = x4[(size_t)dC * 32 + lane];
            float4 vD = x4[(size_t)dD * 32 + lane];
            acc.x = fmaf(aA, vA.x, acc.x); acc.y = fmaf(aA, vA.y, acc.y);
            acc.z = fmaf(aA, vA.z, acc.z); acc.w = fmaf(aA, vA.w, acc.w);
            acc.x = fmaf(aB, vB.x, acc.x); acc.y = fmaf(aB, vB.y, acc.y);
            acc.z = fmaf(aB, vB.z, acc.z); acc.w = fmaf(aB, vB.w, acc.w);
            acc.x = fmaf(aC, vC.x, acc.x); acc.y = fmaf(aC, vC.y, acc.y);
            acc.z = fmaf(aC, vC.z, acc.z); acc.w = fmaf(aC, vC.w, acc.w);
            acc.x = fmaf(aD, vD.x, acc.x); acc.y = fmaf(aD, vD.y, acc.y);
            acc.z = fmaf(aD, vD.z, acc.z); acc.w = fmaf(aD, vD.w, acc.w);
        }
        for (; j < cnt; j++) {
            unsigned d = __shfl_sync(0xffffffffu, meta.x, j);
            float a = __uint_as_float(__shfl_sync(0xffffffffu, meta.y, j));
            float4 v = x4[(size_t)d * 32 + lane];
            acc.x = fmaf(a, v.x, acc.x); acc.y = fmaf(a, v.y, acc.y);
            acc.z = fmaf(a, v.z, acc.z); acc.w = fmaf(a, v.w, acc.w);
        }
    }
    ((float4*)g_Y)[(size_t)n * 32 + lane] = acc;
}

// ---------------- out = y @ (I + ft_w) + ft_b  (fp32x2 FFMA2 tiled GEMM) ----------------
__global__ __launch_bounds__(256) void k_out(const float* __restrict__ ftb,
                                             float* __restrict__ out) {
    extern __shared__ float sm[];
    float* sG = sm;            // 128*128
    float* sYT = sm + 16384;   // 16 x 68 (k-major, padded)
    int t = threadIdx.x;
    int tx = t & 15, ty = t >> 4;
#pragma unroll
    for (int j = 0; j < 64; j++) sG[t + j * 256] = g_G[t + j * 256];
    unsigned long long acc[4][4];
#pragma unroll
    for (int i = 0; i < 4; i++)
#pragma unroll
        for (int j = 0; j < 4; j++) acc[i][j] = 0ull;
    int m0 = blockIdx.x * 64;
    for (int kc = 0; kc < 8; kc++) {
        __syncthreads();
#pragma unroll
        for (int j = 0; j < 4; j++) {
            int idx = t + j * 256;        // 1024
            int c = idx & 15, r = idx >> 4;
            sYT[c * 68 + r] = g_Y[(size_t)(m0 + r) * 128 + kc * 16 + c];
        }
        __syncthreads();
#pragma unroll
        for (int k = 0; k < 16; k++) {
            float4 av = *(float4*)(sYT + k * 68 + ty * 4);
            const unsigned long long* bp =
                (const unsigned long long*)(sG + (kc * 16 + k) * 128 + tx * 8);
            unsigned long long b0 = bp[0], b1 = bp[1], b2 = bp[2], b3 = bp[3];
            unsigned long long a0 = pk2(av.x, av.x);
            unsigned long long a1 = pk2(av.y, av.y);
            unsigned long long a2 = pk2(av.z, av.z);
            unsigned long long a3 = pk2(av.w, av.w);
            fma2(acc[0][0], a0, b0); fma2(acc[0][1], a0, b1);
            fma2(acc[0][2], a0, b2); fma2(acc[0][3], a0, b3);
            fma2(acc[1][0], a1, b0); fma2(acc[1][1], a1, b1);
            fma2(acc[1][2], a1, b2); fma2(acc[1][3], a1, b3);
            fma2(acc[2][0], a2, b0); fma2(acc[2][1], a2, b1);
            fma2(acc[2][2], a2, b2); fma2(acc[2][3], a2, b3);
            fma2(acc[3][0], a3, b0); fma2(acc[3][1], a3, b1);
            fma2(acc[3][2], a3, b2); fma2(acc[3][3], a3, b3);
        }
    }
    float4 fb0 = ((const float4*)ftb)[tx * 2];
    float4 fb1 = ((const float4*)ftb)[tx * 2 + 1];
#pragma unroll
    for (int i = 0; i < 4; i++) {
        float2 p0 = upk2(acc[i][0]), p1 = upk2(acc[i][1]);
        float2 p2 = upk2(acc[i][2]), p3 = upk2(acc[i][3]);
        float4 o0 = make_float4(p0.x + fb0.x, p0.y + fb0.y, p1.x + fb0.z, p1.y + fb0.w);
        float4 o1 = make_float4(p2.x + fb1.x, p2.y + fb1.y, p3.x + fb1.z, p3.y + fb1.w);
        float4* op = (float4*)(out + (size_t)(m0 + ty * 4 + i) * 128 + tx * 8);
        op[0] = o0;
        op[1] = o1;
    }
}

// ---------------- launch ----------------
extern "C" void kernel_launch(void* const* d_in, const int* in_sizes, int n_in,
                              void* d_out, int out_size) {
    const float* x   = (const float*)d_in[0];
    const void*  ei  = d_in[1];
    const float* ea  = (const float*)d_in[2];
    const float* Whw = (const float*)d_in[3];
    const float* Whb = (const float*)d_in[4];
    const float* Wnw = (const float*)d_in[5];
    const float* Wnb = (const float*)d_in[6];
    const float* we  = (const float*)d_in[7];
    const float* ftw = (const float*)d_in[8];
    const float* ftb = (const float*)d_in[9];
    float* out = (float*)d_out;

    cudaFuncSetAttribute(k_node, cudaFuncAttributeMaxDynamicSharedMemorySize, 52224);
    cudaFuncSetAttribute(k_out,  cudaFuncAttributeMaxDynamicSharedMemorySize, 69888);

    k_prep<<<160, 256>>>(Whw, Whb, Wnw, Wnb, ftw, (const int*)ei);
    k_node<<<dim3(625, 2), 128, 52224>>>(x);
    k_edge<<<10000, 128>>>(ea, ei, we);
    k_histZ<<<2500, 256>>>(ei);
    k_scan<<<1, 1024>>>();
    k_fill<<<2500, 256>>>(ei);
    k_gather<<<5000, 256>>>((const float4*)x);
    k_out<<<625, 256, 69888>>>(ftb, out);
}

// round 11
// speedup vs baseline: 1.1277x; 1.0950x over previous
#include <cuda_runtime.h>
#include <cuda_bf16.h>
#include <cstdint>

#define NN 40000
#define EE 640000

// ---------------- static device scratch (no allocs allowed) ----------------
__device__ __align__(16) unsigned g_AB[(size_t)NN * 128]; // bf16 pairs: [node][128 u32]; 0..63 = a, 64..127 = b
__device__ __align__(16) unsigned g_Xbf[(size_t)NN * 64]; // bf16 image of x: [node][64 u32]
__device__ __align__(16) float    g_S[EE];                // raw scores, then exp(s-m)
__device__ __align__(16) float    g_Y[(size_t)NN * 128];  // y = x + local
__device__ __align__(16) unsigned g_WhT[128 * 32];        // Wh^T bf16 pairs
__device__ __align__(16) unsigned g_WcT[256 * 64];        // combined node-W^T bf16 pairs
__device__ __align__(16) float    g_G[128 * 128];         // I + ft_w
__device__ float    g_bias[128];                          // Wh_b + Wn_b
__device__ unsigned g_maxenc;
__device__ float    g_Z;
__device__ int      g_idx64;

// ---------------- helpers ----------------
__device__ __forceinline__ unsigned packbf(float a, float b) {
    unsigned lo = (unsigned)__bfloat16_as_ushort(__float2bfloat16_rn(a));
    unsigned hi = (unsigned)__bfloat16_as_ushort(__float2bfloat16_rn(b));
    return lo | (hi << 16);
}
__device__ __forceinline__ float2 bf2(unsigned u) {
    float2 r;
    r.x = __uint_as_float(u << 16);
    r.y = __uint_as_float(u & 0xffff0000u);
    return r;
}
// order-preserving float<->uint encode for atomicMax
__device__ __forceinline__ unsigned encf(float f) {
    unsigned b = __float_as_uint(f);
    return (b & 0x80000000u) ? ~b : (b | 0x80000000u);
}
__device__ __forceinline__ float decf(unsigned u) {
    unsigned b = (u & 0x80000000u) ? (u & 0x7fffffffu) : ~u;
    return __uint_as_float(b);
}
__device__ __forceinline__ void mma16816(float& c0, float& c1, float& c2, float& c3,
                                         unsigned a0, unsigned a1, unsigned a2, unsigned a3,
                                         unsigned b0, unsigned b1) {
    asm volatile(
        "mma.sync.aligned.m16n8k16.row.col.f32.bf16.bf16.f32 "
        "{%0,%1,%2,%3},{%4,%5,%6,%7},{%8,%9},{%0,%1,%2,%3};\n"
        : "+f"(c0), "+f"(c1), "+f"(c2), "+f"(c3)
        : "r"(a0), "r"(a1), "r"(a2), "r"(a3), "r"(b0), "r"(b1));
}
// packed fp32x2 FMA (FFMA2 — 2x fp32 FMA throughput, PTX-only pattern)
__device__ __forceinline__ void fma2(unsigned long long& c, unsigned long long a,
                                     unsigned long long b) {
    asm("fma.rn.f32x2 %0, %1, %2, %0;" : "+l"(c) : "l"(a), "l"(b));
}
__device__ __forceinline__ unsigned long long pk2(float x, float y) {
    unsigned long long r;
    asm("mov.b64 %0, {%1,%2};" : "=l"(r) : "f"(x), "f"(y));
    return r;
}
__device__ __forceinline__ float2 upk2(unsigned long long v) {
    float2 f;
    asm("mov.b64 {%0,%1}, %2;" : "=f"(f.x), "=f"(f.y) : "l"(v));
    return f;
}

// ---------------- prep: weights, flags, y=x copy, bf16 x image ----------------
__global__ void k_prep(const float* __restrict__ x,
                       const float* __restrict__ Whw, const float* __restrict__ Whb,
                       const float* __restrict__ Wnw, const float* __restrict__ Wnb,
                       const float* __restrict__ ftw, const int* __restrict__ eiw) {
    int gid = blockIdx.x * blockDim.x + threadIdx.x; // 2560*256 = 655360
    // y = x  and  g_Xbf = bf16(x)   (NN*32 = 1.28M float4, 2 iters)
    for (int i = gid; i < NN * 32; i += 655360) {
        float4 v = ((const float4*)x)[i];
        ((float4*)g_Y)[i] = v;
        g_Xbf[i * 2]     = packbf(v.x, v.y);
        g_Xbf[i * 2 + 1] = packbf(v.z, v.w);
    }
    // WhT pairs: 128 n x 32 k-pairs
    if (gid < 4096) {
        int n = gid >> 5, k2 = gid & 31;
        int k = k2 * 2;
        g_WhT[gid] = packbf(Whw[k * 128 + n], Whw[(k + 1) * 128 + n]);
    }
    // WcT pairs: 256 ncomb x 64 k-pairs. ncomb = part*128 + hid
    if (gid < 16384) {
        int ncomb = gid >> 6, k2 = gid & 63;
        int k = k2 * 2;
        int row0 = (ncomb >> 7) * 128 + k;
        int col = ncomb & 127;
        g_WcT[gid] = packbf(Wnw[row0 * 128 + col], Wnw[(row0 + 1) * 128 + col]);
    }
    // G = I + ft_w
    if (gid < 16384) {
        g_G[gid] = ftw[gid] + (((gid >> 7) == (gid & 127)) ? 1.0f : 0.0f);
    }
    if (gid < 128) g_bias[gid] = Whb[gid] + Wnb[gid];
    if (gid == 0) {
        int o = 0;
#pragma unroll
        for (int i = 0; i < 64; i++) o |= eiw[2 * i + 1];
        g_idx64 = (o == 0) ? 1 : 0;
        g_maxenc = 0u;
        g_Z = 0.0f;
    }
}

// ---------------- node projection: g_AB = bf16( x @ [Wn_a | Wn_b] ) via mma ----------------
__global__ __launch_bounds__(128) void k_node(const float* __restrict__ x) {
    extern __shared__ unsigned smu[];
    unsigned* sX = smu;              // 64 rows x 68 (pad) u32 (k pairs)
    unsigned* sW = smu + 64 * 68;    // 128 n-rows x 68 (pad) u32
    int t = threadIdx.x;
    int node0 = blockIdx.x * 64;
    int part = blockIdx.y;           // 0 -> a cols, 1 -> b cols
    const float2* xp = (const float2*)x;
#pragma unroll
    for (int j = 0; j < 32; j++) {
        int idx = t + j * 128;       // 4096
        int r = idx >> 6, c = idx & 63;
        float2 f = xp[(size_t)(node0 + r) * 64 + c];
        sX[r * 68 + c] = packbf(f.x, f.y);
    }
#pragma unroll
    for (int j = 0; j < 64; j++) {
        int idx = t + j * 128;       // 8192
        int n = idx >> 6, k = idx & 63;
        sW[n * 68 + k] = g_WcT[(size_t)(part * 128 + n) * 64 + k];
    }
    __syncthreads();
    int warp = t >> 5, lane = t & 31, g = lane >> 2, q = lane & 3;
    int m0 = warp * 16;
#pragma unroll
    for (int nt = 0; nt < 16; nt++) {
        float c0 = 0.f, c1 = 0.f, c2 = 0.f, c3 = 0.f;
#pragma unroll
        for (int kc = 0; kc < 8; kc++) {
            unsigned a0 = sX[(m0 + g) * 68 + kc * 8 + q];
            unsigned a1 = sX[(m0 + g + 8) * 68 + kc * 8 + q];
            unsigned a2 = sX[(m0 + g) * 68 + kc * 8 + q + 4];
            unsigned a3 = sX[(m0 + g + 8) * 68 + kc * 8 + q + 4];
            unsigned b0 = sW[(nt * 8 + g) * 68 + kc * 8 + q];
            unsigned b1 = sW[(nt * 8 + g) * 68 + kc * 8 + q + 4];
            mma16816(c0, c1, c2, c3, a0, a1, a2, a3, b0, b1);
        }
        int node = node0 + m0 + g;
        int u = part * 64 + nt * 4 + q;
        g_AB[(size_t)node * 128 + u] = packbf(c0, c1);
        g_AB[(size_t)(node + 8) * 128 + u] = packbf(c2, c3);
    }
}

// ---------------- fused edge kernel: scores + block max ----------------
__global__ __launch_bounds__(128) void k_edge(const float* __restrict__ ea,
                                              const void* __restrict__ ei,
                                              const float* __restrict__ we) {
    __shared__ unsigned sWh[128 * 36];
    __shared__ float swe[128];
    __shared__ float sbias[128];
    __shared__ float smax[4];
    int t = threadIdx.x;
#pragma unroll
    for (int j = 0; j < 32; j++) {
        int idx = t + j * 128;
        int n = idx >> 5, k = idx & 31;
        sWh[n * 36 + k] = g_WhT[idx];
    }
    swe[t & 127] = we[t & 127];
    sbias[t & 127] = g_bias[t & 127];
    __syncthreads();

    int warp = t >> 5, lane = t & 31, g = lane >> 2, q = lane & 3;
    int e0 = (blockIdx.x * 4 + warp) * 16;
    int r0 = e0 + g, r1 = r0 + 8;
    int s0, d0, s1, d1;
    if (g_idx64) {
        const long long* p = (const long long*)ei;
        s0 = (int)p[r0]; d0 = (int)p[(long long)EE + r0];
        s1 = (int)p[r1]; d1 = (int)p[(long long)EE + r1];
    } else {
        const int* p = (const int*)ei;
        s0 = p[r0]; d0 = p[EE + r0];
        s1 = p[r1]; d1 = p[EE + r1];
    }
    unsigned a[4][4];
    const float2* ear0 = (const float2*)ea + (size_t)r0 * 32;
    const float2* ear1 = (const float2*)ea + (size_t)r1 * 32;
#pragma unroll
    for (int kc = 0; kc < 4; kc++) {
        float2 f;
        f = ear0[kc * 8 + q];     a[kc][0] = packbf(f.x, f.y);
        f = ear1[kc * 8 + q];     a[kc][1] = packbf(f.x, f.y);
        f = ear0[kc * 8 + q + 4]; a[kc][2] = packbf(f.x, f.y);
        f = ear1[kc * 8 + q + 4]; a[kc][3] = packbf(f.x, f.y);
    }
    const unsigned* as0p = g_AB + (size_t)s0 * 128;
    const unsigned* bd0p = g_AB + (size_t)d0 * 128 + 64;
    const unsigned* as1p = g_AB + (size_t)s1 * 128;
    const unsigned* bd1p = g_AB + (size_t)d1 * 128 + 64;
    float sacc0 = 0.f, sacc1 = 0.f;
#pragma unroll
    for (int nt = 0; nt < 16; nt++) {
        float c0 = 0.f, c1 = 0.f, c2 = 0.f, c3 = 0.f;
#pragma unroll
        for (int kc = 0; kc < 4; kc++) {
            unsigned b0 = sWh[(nt * 8 + g) * 36 + kc * 8 + q];
            unsigned b1 = sWh[(nt * 8 + g) * 36 + kc * 8 + q + 4];
            mma16816(c0, c1, c2, c3, a[kc][0], a[kc][1], a[kc][2], a[kc][3], b0, b1);
        }
        int n0 = nt * 8 + q * 2;
        float wx = swe[n0], wy = swe[n0 + 1];
        float bx = sbias[n0], by = sbias[n0 + 1];
        int u = nt * 4 + q;
        float2 A0 = bf2(as0p[u]); float2 B0 = bf2(bd0p[u]);
        float2 A1 = bf2(as1p[u]); float2 B1 = bf2(bd1p[u]);
        float v;
        v = c0 + A0.x + B0.x + bx; v = fmaxf(v, 0.f); sacc0 = fmaf(v, wx, sacc0);
        v = c1 + A0.y + B0.y + by; v = fmaxf(v, 0.f); sacc0 = fmaf(v, wy, sacc0);
        v = c2 + A1.x + B1.x + bx; v = fmaxf(v, 0.f); sacc1 = fmaf(v, wx, sacc1);
        v = c3 + A1.y + B1.y + by; v = fmaxf(v, 0.f); sacc1 = fmaf(v, wy, sacc1);
    }
    sacc0 += __shfl_xor_sync(0xffffffffu, sacc0, 1);
    sacc0 += __shfl_xor_sync(0xffffffffu, sacc0, 2);
    sacc1 += __shfl_xor_sync(0xffffffffu, sacc1, 1);
    sacc1 += __shfl_xor_sync(0xffffffffu, sacc1, 2);
    if (q == 0) { g_S[r0] = sacc0; g_S[r1] = sacc1; }
    float mx = fmaxf(sacc0, sacc1);
#pragma unroll
    for (int o = 16; o; o >>= 1) mx = fmaxf(mx, __shfl_xor_sync(0xffffffffu, mx, o));
    if (lane == 0) smax[warp] = mx;
    __syncthreads();
    if (t == 0) {
        float m = fmaxf(fmaxf(smax[0], smax[1]), fmaxf(smax[2], smax[3]));
        atomicMax(&g_maxenc, encf(m));
    }
}

// ---------------- Z = sum exp(s - m); writes exp back to g_S ----------------
__global__ void k_Zred() {
    __shared__ float ssum[8];
    float m = decf(g_maxenc);
    int gid = blockIdx.x * blockDim.x + threadIdx.x; // 2500*256 = 640000 exactly
    float s = 0.f;
    if (gid < EE) {
        s = __expf(g_S[gid] - m);
        g_S[gid] = s;
    }
#pragma unroll
    for (int o = 16; o; o >>= 1) s += __shfl_xor_sync(0xffffffffu, s, o);
    if ((threadIdx.x & 31) == 0) ssum[threadIdx.x >> 5] = s;
    __syncthreads();
    if (threadIdx.x == 0) {
        float b = 0.f;
#pragma unroll
        for (int i = 0; i < 8; i++) b += ssum[i];
        atomicAdd(&g_Z, b);
    }
}

// ---------------- scatter: y[src] -= alpha * x[dst]; bf16 gather, fp32 red ----------------
__global__ __launch_bounds__(256) void k_scatter(const void* __restrict__ ei) {
    int e = blockIdx.x * 8 + (threadIdx.x >> 5);
    if (e >= EE) return;
    int lane = threadIdx.x & 31;
    float alpha = __fdividef(g_S[e], g_Z);
    int s, d;
    if (g_idx64) {
        const long long* p = (const long long*)ei;
        s = (int)p[e]; d = (int)p[(long long)EE + e];
    } else {
        const int* p = (const int*)ei;
        s = p[e]; d = p[EE + e];
    }
    uint2 xb = ((const uint2*)g_Xbf)[(size_t)d * 32 + lane]; // 4 bf16 per lane
    float2 lo = bf2(xb.x), hi = bf2(xb.y);
    float c = -alpha;
    float* ptr = g_Y + (size_t)s * 128 + lane * 4;
    asm volatile("red.global.add.v4.f32 [%0], {%1,%2,%3,%4};"
                 :: "l"(ptr), "f"(c * lo.x), "f"(c * lo.y), "f"(c * hi.x), "f"(c * hi.y)
                 : "memory");
}

// ---------------- out = y @ (I + ft_w) + ft_b  (fp32x2 FFMA2 tiled GEMM) ----------------
__global__ __launch_bounds__(256) void k_out(const float* __restrict__ ftb,
                                             float* __restrict__ out) {
    extern __shared__ float sm[];
    float* sG = sm;            // 128*128
    float* sYT = sm + 16384;   // 16 x 68 (k-major, padded)
    int t = threadIdx.x;
    int tx = t & 15, ty = t >> 4;
#pragma unroll
    for (int j = 0; j < 64; j++) sG[t + j * 256] = g_G[t + j * 256];
    unsigned long long acc[4][4];
#pragma unroll
    for (int i = 0; i < 4; i++)
#pragma unroll
        for (int j = 0; j < 4; j++) acc[i][j] = 0ull;
    int m0 = blockIdx.x * 64;
    for (int kc = 0; kc < 8; kc++) {
        __syncthreads();
#pragma unroll
        for (int j = 0; j < 4; j++) {
            int idx = t + j * 256;        // 1024
            int c = idx & 15, r = idx >> 4;
            sYT[c * 68 + r] = g_Y[(size_t)(m0 + r) * 128 + kc * 16 + c];
        }
        __syncthreads();
#pragma unroll
        for (int k = 0; k < 16; k++) {
            float4 av = *(float4*)(sYT + k * 68 + ty * 4);
            const unsigned long long* bp =
                (const unsigned long long*)(sG + (kc * 16 + k) * 128 + tx * 8);
            unsigned long long b0 = bp[0], b1 = bp[1], b2 = bp[2], b3 = bp[3];
            unsigned long long a0 = pk2(av.x, av.x);
            unsigned long long a1 = pk2(av.y, av.y);
            unsigned long long a2 = pk2(av.z, av.z);
            unsigned long long a3 = pk2(av.w, av.w);
            fma2(acc[0][0], a0, b0); fma2(acc[0][1], a0, b1);
            fma2(acc[0][2], a0, b2); fma2(acc[0][3], a0, b3);
            fma2(acc[1][0], a1, b0); fma2(acc[1][1], a1, b1);
            fma2(acc[1][2], a1, b2); fma2(acc[1][3], a1, b3);
            fma2(acc[2][0], a2, b0); fma2(acc[2][1], a2, b1);
            fma2(acc[2][2], a2, b2); fma2(acc[2][3], a2, b3);
            fma2(acc[3][0], a3, b0); fma2(acc[3][1], a3, b1);
            fma2(acc[3][2], a3, b2); fma2(acc[3][3], a3, b3);
        }
    }
    float4 fb0 = ((const float4*)ftb)[tx * 2];
    float4 fb1 = ((const float4*)ftb)[tx * 2 + 1];
#pragma unroll
    for (int i = 0; i < 4; i++) {
        float2 p0 = upk2(acc[i][0]), p1 = upk2(acc[i][1]);
        float2 p2 = upk2(acc[i][2]), p3 = upk2(acc[i][3]);
        float4 o0 = make_float4(p0.x + fb0.x, p0.y + fb0.y, p1.x + fb0.z, p1.y + fb0.w);
        float4 o1 = make_float4(p2.x + fb1.x, p2.y + fb1.y, p3.x + fb1.z, p3.y + fb1.w);
        float4* op = (float4*)(out + (size_t)(m0 + ty * 4 + i) * 128 + tx * 8);
        op[0] = o0;
        op[1] = o1;
    }
}

// ---------------- launch ----------------
extern "C" void kernel_launch(void* const* d_in, const int* in_sizes, int n_in,
                              void* d_out, int out_size) {
    const float* x   = (const float*)d_in[0];
    const void*  ei  = d_in[1];
    const float* ea  = (const float*)d_in[2];
    const float* Whw = (const float*)d_in[3];
    const float* Whb = (const float*)d_in[4];
    const float* Wnw = (const float*)d_in[5];
    const float* Wnb = (const float*)d_in[6];
    const float* we  = (const float*)d_in[7];
    const float* ftw = (const float*)d_in[8];
    const float* ftb = (const float*)d_in[9];
    float* out = (float*)d_out;

    cudaFuncSetAttribute(k_node, cudaFuncAttributeMaxDynamicSharedMemorySize, 52224);
    cudaFuncSetAttribute(k_out,  cudaFuncAttributeMaxDynamicSharedMemorySize, 69888);

    k_prep<<<2560, 256>>>(x, Whw, Whb, Wnw, Wnb, ftw, (const int*)ei);
    k_node<<<dim3(625, 2), 128, 52224>>>(x);
    k_edge<<<10000, 128>>>(ea, ei, we);
    k_Zred<<<2500, 256>>>();
    k_scatter<<<80000, 256>>>(ei);
    k_out<<<625, 256, 69888>>>(ftb, out);
}